// round 15
// baseline (speedup 1.0000x reference)
#include <cuda_runtime.h>
#include <cuda_bf16.h>
#include <math.h>
#include <cstdint>

#define D     128
#define Mn    128
#define KTAB  64
#define KSEL  32
#define Bq    2048
#define FEW   5
#define DM    256
#define HID   512
#define NL    1024
#define NTASK (2 * Bq + 2 * FEW)
#define TPAD  4224
#define TQ    2176
#define PREPB 1632

typedef unsigned long long ull;
typedef unsigned int u32;

// ================= scratch =================
__device__ __align__(128) float g_qn[TQ * DM];
__device__ __align__(128) float g_qg[TQ * DM];
__device__ __align__(128) float g_sg[DM];
__device__ __align__(128) float g_sgn[DM];
__device__ __align__(128) float g_vr[NL];
__device__ __align__(128) float g_pb[NL];
__device__ __align__(128) float g_qp[(size_t)Bq * NL];
__device__ __align__(128) float g_cst[Bq * DM];
__device__ __align__(128) float g_hb[Bq * DM];
__device__ __align__(128) u32 g_hshi[TPAD * 128];
__device__ __align__(128) u32 g_hslo[TPAD * 128];
__device__ __align__(128) u32 g_hkhi[TPAD * 64];
__device__ __align__(128) u32 g_hklo[TPAD * 64];
__device__ __align__(128) u32 g_qnhi[TQ * 128];
__device__ __align__(128) u32 g_qnlo[TQ * 128];
__device__ __align__(128) u32 g_acthi[TQ * 256];
__device__ __align__(128) u32 g_actlo[TQ * 256];
__device__ __align__(128) u32 g_qghi[Bq * 128];
__device__ __align__(128) u32 g_qglo[Bq * 128];
__device__ __align__(128) u32 g_hahi[Bq * 128];
__device__ __align__(128) u32 g_halo[Bq * 128];
__device__ __align__(128) u32 g_hbhi[Bq * 128];
__device__ __align__(128) u32 g_hblo[Bq * 128];
__device__ __align__(128) u32 g_wihh[NL * 128];
__device__ __align__(128) u32 g_wihl[NL * 128];
__device__ __align__(128) u32 g_whhh[NL * 128];
__device__ __align__(128) u32 g_whhl[NL * 128];
__device__ __align__(128) u32 g_gwh[128 * 128];
__device__ __align__(128) u32 g_gwl[128 * 128];
__device__ __align__(128) u32 g_gkh[128 * 64];
__device__ __align__(128) u32 g_gkl[128 * 64];
__device__ __align__(128) u32 g_p1h[512 * 128];
__device__ __align__(128) u32 g_p1l[512 * 128];
__device__ __align__(128) u32 g_p2h[256 * 256];
__device__ __align__(128) u32 g_p2l[256 * 256];

__device__ __forceinline__ float wred(float v) {
#pragma unroll
    for (int o = 16; o; o >>= 1) v += __shfl_xor_sync(0xffffffffu, v, o);
    return v;
}
__device__ __forceinline__ float sigmf(float x) { return 1.f / (1.f + expf(-x)); }
__device__ __forceinline__ void splitpack(float a, float b, u32& hi, u32& lo) {
    __nv_bfloat16 ha = __float2bfloat16(a), hb2 = __float2bfloat16(b);
    __nv_bfloat16 la = __float2bfloat16(a - __bfloat162float(ha));
    __nv_bfloat16 lb = __float2bfloat16(b - __bfloat162float(hb2));
    __nv_bfloat162 H; H.x = ha; H.y = hb2;
    __nv_bfloat162 L; L.x = la; L.y = lb;
    hi = *(u32*)&H; lo = *(u32*)&L;
}
__device__ __forceinline__ int nperm_src(int n) {
    int b = n >> 4, r = n & 15;
    int v = (r & 7) >> 1;
    int g = (r >> 3) * 2 + (r & 1);
    return g * 512 + b * 4 + v;
}
__device__ __forceinline__ u32 smem_u32(const void* p) {
    u32 a;
    asm("{ .reg .u64 t; cvta.to.shared.u64 t, %1; cvt.u32.u64 %0, t; }" : "=r"(a) : "l"(p));
    return a;
}
__device__ __forceinline__ void ldm4(u32* r, u32 addr) {
    asm volatile("ldmatrix.sync.aligned.m8n8.x4.shared.b16 {%0,%1,%2,%3}, [%4];"
                 : "=r"(r[0]), "=r"(r[1]), "=r"(r[2]), "=r"(r[3]) : "r"(addr));
}
__device__ __forceinline__ void mma16816(float* d, const u32* a, const u32* b) {
    asm volatile("mma.sync.aligned.m16n8k16.row.col.f32.bf16.bf16.f32 "
                 "{%0,%1,%2,%3},{%4,%5,%6,%7},{%8,%9},{%0,%1,%2,%3};"
                 : "+f"(d[0]), "+f"(d[1]), "+f"(d[2]), "+f"(d[3])
                 : "r"(a[0]), "r"(a[1]), "r"(a[2]), "r"(a[3]), "r"(b[0]), "r"(b[1]));
}

// ================= weight prep bodies =================
__device__ __forceinline__ void prep_perm_body(int idx, const float* w, int ldw,
                                               u32* hi, u32* lo) {
    int n = idx >> 7, kp = idx & 127;
    int srow = nperm_src(n);
    float v0 = w[(size_t)srow * ldw + 2 * kp];
    float v1 = w[(size_t)srow * ldw + 2 * kp + 1];
    u32 h, l;
    splitpack(v0, v1, h, l);
    hi[idx] = h; lo[idx] = l;
}
__device__ __forceinline__ void split_body(int idx, const float* w, int ldw, int off,
                                           int khalf, u32* hi, u32* lo) {
    int n = idx / khalf, kp = idx % khalf;
    float v0 = w[(size_t)n * ldw + off + 2 * kp];
    float v1 = w[(size_t)n * ldw + off + 2 * kp + 1];
    u32 h, l;
    splitpack(v0, v1, h, l);
    hi[idx] = h; lo[idx] = l;
}

// ================= neighbor gather + fused weight prep =================
__global__ __launch_bounds__(256) void neigh_gather(
    const int* __restrict__ query, const int* __restrict__ support,
    const int* __restrict__ qlc, const int* __restrict__ qrc,
    const int* __restrict__ slc, const int* __restrict__ src_,
    const int* __restrict__ knn, const float* __restrict__ emb,
    const float* __restrict__ w_ih, const float* __restrict__ w_hh,
    const float* __restrict__ gcn_w, const float* __restrict__ p1_w,
    const float* __restrict__ p2_w)
{
    __shared__ float s_center[D];
    __shared__ int   s_rid[Mn], s_eid[Mn];
    __shared__ float s_sim[Mn];
    __shared__ int   s_kid[KTAB];
    __shared__ float s_ksim[KTAB];
    __shared__ int   s_selr[KSEL], s_sele[KSEL], s_kselv[KSEL];
    __shared__ int   s_cnt, s_kcnt;
    __shared__ float s_cn;
    __shared__ float e_hs[DM];
    __shared__ float e_hk[D];

    if (blockIdx.x >= NTASK) {
        int b = blockIdx.x - NTASK, tid = threadIdx.x;
        if (b < 512)        prep_perm_body(b * 256 + tid, w_ih, DM, g_wihh, g_wihl);
        else if (b < 1024)  prep_perm_body((b - 512) * 256 + tid, w_hh, HID, g_whhh, g_whhl);
        else if (b < 1088)  split_body((b - 1024) * 256 + tid, gcn_w, 256, 0, 128, g_gwh, g_gwl);
        else if (b < 1120)  split_body((b - 1088) * 256 + tid, gcn_w, 256, 128, 64, g_gkh, g_gkl);
        else if (b < 1376)  split_body((b - 1120) * 256 + tid, p1_w, 256, 0, 128, g_p1h, g_p1l);
        else                split_body((b - 1376) * 256 + tid, p2_w, 512, 0, 256, g_p2h, g_p2l);
        return;
    }

    int task = blockIdx.x;
    const int* conn; int id;
    if (task < 2 * Bq) {
        int row = task & (Bq - 1);
        int br  = task >> 11;
        conn = (br ? qrc : qlc) + (size_t)row * Mn * 2;
        id   = query[row * 2 + br];
    } else {
        int t = task - 2 * Bq;
        int br = t / FEW, row = t % FEW;
        conn = (br ? src_ : slc) + (size_t)row * Mn * 2;
        id   = support[row * 2 + br];
    }
    int tid = threadIdx.x, lane = tid & 31, wid = tid >> 5;
    if (tid == 0) { s_cnt = 0; s_kcnt = 0; }
    if (tid < D)  s_center[tid] = emb[(size_t)id * D + tid];
    if (tid < Mn) { s_rid[tid] = conn[tid * 2]; s_eid[tid] = conn[tid * 2 + 1]; }
    if (tid >= 192) s_kid[tid - 192] = knn[(size_t)id * KTAB + (tid - 192)];
    __syncthreads();

    if (wid == 0) {
        float c0 = s_center[lane], c1 = s_center[lane + 32],
              c2 = s_center[lane + 64], c3 = s_center[lane + 96];
        float s = wred(c0 * c0 + c1 * c1 + c2 * c2 + c3 * c3);
        if (lane == 0) s_cn = sqrtf(s);
    }
    __syncthreads();
    float cn = s_cn;
    float4 cv = ((const float4*)s_center)[lane];

#pragma unroll
    for (int g = 0; g < 4; g++) {
        int m = wid * 16 + g * 4;
        float dt[4], nn[4];
#pragma unroll
        for (int t = 0; t < 4; t++) {
            float4 ev = ((const float4*)(emb + (size_t)s_eid[m + t] * D))[lane];
            dt[t] = ev.x * cv.x + ev.y * cv.y + ev.z * cv.z + ev.w * cv.w;
            nn[t] = ev.x * ev.x + ev.y * ev.y + ev.z * ev.z + ev.w * ev.w;
        }
#pragma unroll
        for (int o = 16; o; o >>= 1) {
#pragma unroll
            for (int t = 0; t < 4; t++) {
                dt[t] += __shfl_xor_sync(0xffffffffu, dt[t], o);
                nn[t] += __shfl_xor_sync(0xffffffffu, nn[t], o);
            }
        }
        if (lane == 0) {
#pragma unroll
            for (int t = 0; t < 4; t++)
                s_sim[m + t] = dt[t] / fmaxf(cn * sqrtf(nn[t]), 1e-8f);
        }
    }
#pragma unroll
    for (int g = 0; g < 2; g++) {
        int m = wid * 8 + g * 4;
        float dt[4], nn[4];
#pragma unroll
        for (int t = 0; t < 4; t++) {
            float4 ev = ((const float4*)(emb + (size_t)s_kid[m + t] * D))[lane];
            dt[t] = ev.x * cv.x + ev.y * cv.y + ev.z * cv.z + ev.w * cv.w;
            nn[t] = ev.x * ev.x + ev.y * ev.y + ev.z * ev.z + ev.w * ev.w;
        }
#pragma unroll
        for (int o = 16; o; o >>= 1) {
#pragma unroll
            for (int t = 0; t < 4; t++) {
                dt[t] += __shfl_xor_sync(0xffffffffu, dt[t], o);
                nn[t] += __shfl_xor_sync(0xffffffffu, nn[t], o);
            }
        }
        if (lane == 0) {
#pragma unroll
            for (int t = 0; t < 4; t++)
                s_ksim[m + t] = dt[t] / fmaxf(cn * sqrtf(nn[t]), 1e-8f);
        }
    }
    __syncthreads();

    if (tid < Mn) {
        float v = s_sim[tid]; int r = 0;
        for (int j = 0; j < Mn; j++) {
            float u = s_sim[j];
            r += (u > v) || (u == v && j < tid);
        }
        if (r < KSEL) {
            int p = atomicAdd(&s_cnt, 1);
            s_selr[p] = s_rid[tid];
            s_sele[p] = s_eid[tid];
        }
    } else if (tid < Mn + KTAB) {
        int m = tid - Mn;
        float v = s_ksim[m]; int r = 0;
        for (int j = 0; j < KTAB; j++) {
            float u = s_ksim[j];
            r += (u > v) || (u == v && j < m);
        }
        if (r < KSEL) {
            int p = atomicAdd(&s_kcnt, 1);
            s_kselv[p] = s_kid[m];
        }
    }
    __syncthreads();

    int d = tid & (D - 1);
    if (tid < D) {
        float acc = 0.f;
#pragma unroll 8
        for (int i = 0; i < KSEL; i++) acc += emb[(size_t)s_selr[i] * D + d];
        e_hs[d] = acc * (1.f / KSEL);
        float ak = 0.f;
#pragma unroll 8
        for (int i = 0; i < KSEL; i++) ak += emb[(size_t)s_kselv[i] * D + d];
        e_hk[d] = ak * (1.f / KSEL);
    } else {
        float acc = 0.f;
#pragma unroll 8
        for (int i = 0; i < KSEL; i++) acc += emb[(size_t)s_sele[i] * D + d];
        e_hs[D + d] = acc * (1.f / KSEL);
    }
    __syncthreads();
    if (tid < 128) {
        u32 hi, lo;
        splitpack(e_hs[2 * tid], e_hs[2 * tid + 1], hi, lo);
        g_hshi[(size_t)task * 128 + tid] = hi;
        g_hslo[(size_t)task * 128 + tid] = lo;
    } else if (tid < 192) {
        int t2 = tid - 128;
        u32 hi, lo;
        splitpack(e_hk[2 * t2], e_hk[2 * t2 + 1], hi, lo);
        g_hkhi[(size_t)task * 64 + t2] = hi;
        g_hklo[(size_t)task * 64 + t2] = lo;
    }
}

// ================= double-buffered pipelined mma mainloop =================
#define MMA_PROLOGUE(NG) \
    int tid = threadIdx.x, lane = tid & 31, w = tid >> 5; \
    int wm = (w / (NG)) * 16, wn = (w % (NG)) * (128 / (NG)); \
    constexpr int NF = 128 / (NG) / 16; \
    constexpr int MT2 = (8 / (NG)) * 32; \
    int lrowW = tid >> 1, lsegW = tid & 1; \
    int lrowA = (tid & (MT2 - 1)) >> 1, lsegA = tid & 1; \
    u32 soffW = (u32)(lrowW * 24 + lsegW * 8) * 2; \
    u32 soffA = (u32)(lrowA * 24 + lsegA * 8) * 2; \
    u32 bAh = smem_u32(sAh), bAl = smem_u32(sAl), bWh = smem_u32(sWh), bWl = smem_u32(sWl); \
    u32 abufB = (u32)(MT2 / 2) * 24u * 2u; \
    u32 wbufB = 128u * 24u * 2u; \
    u32 aoff = (u32)((wm + (lane & 15)) * 24 + (lane >> 4) * 8) * 2; \
    u32 boff[NF]; \
    _Pragma("unroll") \
    for (int nf = 0; nf < NF; nf++) { \
        int g = lane >> 3; \
        int row = wn + nf * 16 + (lane & 7) + (g >> 1) * 8; \
        int col = (g & 1) * 8; \
        boff[nf] = (u32)(row * 24 + col) * 2; \
    }

#define MMA_CHUNK(ACC, NCH, NG) \
    { \
        constexpr int NFc = 128 / (NG) / 16; \
        constexpr int MT2c = (8 / (NG)) * 32; \
        if (tid < MT2c) { \
            *(uint4*)((char*)sAh + soffA) = nah; \
            *(uint4*)((char*)sAl + soffA) = nal; \
        } \
        *(uint4*)((char*)sWh + soffW) = nwh; \
        *(uint4*)((char*)sWl + soffW) = nwl; \
        if (1 < (NCH)) { \
            if (tid < MT2c) { nah = gAh[2]; nal = gAl[2]; } \
            nwh = gWh[2]; nwl = gWl[2]; \
        } \
        __syncthreads(); \
        for (int kc = 0; kc < (NCH); kc++) { \
            u32 cb_ = (u32)(kc & 1), nb_ = cb_ ^ 1u; \
            if (kc + 1 < (NCH)) { \
                if (tid < MT2c) { \
                    *(uint4*)((char*)sAh + nb_ * abufB + soffA) = nah; \
                    *(uint4*)((char*)sAl + nb_ * abufB + soffA) = nal; \
                } \
                *(uint4*)((char*)sWh + nb_ * wbufB + soffW) = nwh; \
                *(uint4*)((char*)sWl + nb_ * wbufB + soffW) = nwl; \
            } \
            if (kc + 2 < (NCH)) { \
                if (tid < MT2c) { nah = gAh[(kc + 2) * 2]; nal = gAl[(kc + 2) * 2]; } \
                nwh = gWh[(kc + 2) * 2]; nwl = gWl[(kc + 2) * 2]; \
            } \
            u32 ah[4], al[4], wf[NFc][4]; \
            ldm4(ah, bAh + cb_ * abufB + aoff); \
            ldm4(al, bAl + cb_ * abufB + aoff); \
            _Pragma("unroll") \
            for (int nf = 0; nf < NFc; nf++) ldm4(wf[nf], bWh + cb_ * wbufB + boff[nf]); \
            _Pragma("unroll") \
            for (int nf = 0; nf < NFc; nf++) { \
                mma16816(ACC[nf * 2],     ah, wf[nf]); \
                mma16816(ACC[nf * 2 + 1], ah, wf[nf] + 2); \
                mma16816(ACC[nf * 2],     al, wf[nf]); \
                mma16816(ACC[nf * 2 + 1], al, wf[nf] + 2); \
            } \
            _Pragma("unroll") \
            for (int nf = 0; nf < NFc; nf++) ldm4(wf[nf], bWl + cb_ * wbufB + boff[nf]); \
            _Pragma("unroll") \
            for (int nf = 0; nf < NFc; nf++) { \
                mma16816(ACC[nf * 2],     ah, wf[nf]); \
                mma16816(ACC[nf * 2 + 1], ah, wf[nf] + 2); \
            } \
            __syncthreads(); \
        } \
    }

// ================= fused GCN dual GEMM + combine (NG=2, 64-row tiles) =================
__global__ __launch_bounds__(256) void gcn_fused(
    const float* __restrict__ gcn_w_b, const float* __restrict__ gcn_b,
    const float* __restrict__ gate_w, const float* __restrict__ gate_b)
{
    __shared__ __align__(16) __nv_bfloat16 sAh[2][64][24], sAl[2][64][24],
                                           sWh[2][128][24], sWl[2][128][24];
    __shared__ float s_part[8][16];
    MMA_PROLOGUE(2);
    int bm = blockIdx.x * 64;

    float acc1[8][4], acc2[8][4];
#pragma unroll
    for (int j = 0; j < 8; j++)
#pragma unroll
        for (int c = 0; c < 4; c++) { acc1[j][c] = 0.f; acc2[j][c] = 0.f; }

    {
        const uint4* gAh = (const uint4*)(g_hshi + (size_t)(bm + lrowA) * 128) + lsegA;
        const uint4* gAl = (const uint4*)(g_hslo + (size_t)(bm + lrowA) * 128) + lsegA;
        const uint4* gWh = (const uint4*)(g_gwh + (size_t)lrowW * 128) + lsegW;
        const uint4* gWl = (const uint4*)(g_gwl + (size_t)lrowW * 128) + lsegW;
        uint4 nah, nal;
        if (tid < 128) { nah = gAh[0]; nal = gAl[0]; }
        uint4 nwh = gWh[0], nwl = gWl[0];
        MMA_CHUNK(acc1, 16, 2);
    }
    {
        const uint4* gAh = (const uint4*)(g_hkhi + (size_t)(bm + lrowA) * 64) + lsegA;
        const uint4* gAl = (const uint4*)(g_hklo + (size_t)(bm + lrowA) * 64) + lsegA;
        const uint4* gWh = (const uint4*)(g_gkh + (size_t)lrowW * 64) + lsegW;
        const uint4* gWl = (const uint4*)(g_gkl + (size_t)lrowW * 64) + lsegW;
        uint4 nah, nal;
        if (tid < 128) { nah = gAh[0]; nal = gAl[0]; }
        uint4 nwh = gWh[0], nwl = gWl[0];
        MMA_CHUNK(acc2, 8, 2);
    }

    int q = lane & 3, r4 = lane >> 2;
    float part[2] = {0.f, 0.f};
#pragma unroll
    for (int p = 0; p < 4; p++)
#pragma unroll
        for (int s = 0; s < 2; s++)
#pragma unroll
            for (int c = 0; c < 2; c++) {
                int col = wn + p * 16 + s * 8 + 2 * q + c;
                float wbgb = gcn_w_b[col] + gcn_b[col];
                float gws = gate_w[col], gwk = gate_w[D + col];
#pragma unroll
                for (int rh = 0; rh < 2; rh++) {
                    float sv = tanhf(acc1[2 * p + s][rh * 2 + c] + wbgb);
                    float kv = tanhf(acc2[2 * p + s][rh * 2 + c] + wbgb);
                    acc1[2 * p + s][rh * 2 + c] = sv;
                    acc2[2 * p + s][rh * 2 + c] = kv;
                    part[rh] += gws * sv + gwk * kv;
                }
            }
#pragma unroll
    for (int rh = 0; rh < 2; rh++) {
        float v = part[rh];
        v += __shfl_xor_sync(0xffffffffu, v, 1);
        v += __shfl_xor_sync(0xffffffffu, v, 2);
        part[rh] = v;
    }
    if (q == 0) {
#pragma unroll
        for (int rh = 0; rh < 2; rh++)
            s_part[w][rh * 8 + r4] = part[rh];
    }
    __syncthreads();
    float gb0 = gate_b[0];
#pragma unroll
    for (int rh = 0; rh < 2; rh++) {
        int rl = rh * 8 + r4;
        float tot = s_part[(w >> 1) * 2][rl] + s_part[(w >> 1) * 2 + 1][rl];
        float al = sigmf(tot + gb0);
        int t = bm + wm + r4 + rh * 8;
        int rowq, half;
        if (t < 2 * Bq) { rowq = t & (Bq - 1); half = t >> 11; }
        else if (t < NTASK) { int t2 = t - 2 * Bq; rowq = Bq + t2 % FEW; half = t2 / FEW; }
        else continue;
#pragma unroll
        for (int p = 0; p < 4; p++)
#pragma unroll
            for (int s = 0; s < 2; s++) {
                int col = wn + p * 16 + s * 8 + 2 * q;
                float o0 = (1.f - al) * acc1[2 * p + s][rh * 2]
                         + al * acc2[2 * p + s][rh * 2];
                float o1 = (1.f - al) * acc1[2 * p + s][rh * 2 + 1]
                         + al * acc2[2 * p + s][rh * 2 + 1];
                int colq = half * 128 + col;
                *(float2*)(g_qn + (size_t)rowq * DM + colq) = make_float2(o0, o1);
                u32 h, l;
                splitpack(o0, o1, h, l);
                g_qnhi[(size_t)rowq * 128 + (colq >> 1)] = h;
                g_qnlo[(size_t)rowq * 128 + (colq >> 1)] = l;
            }
    }
}

// ================= generic bf16-split mma GEMM (templated NG) =================
template<int MODE, int NG>
__global__ __launch_bounds__(256) void mma_gemm(
    const u32* __restrict__ ahi, const u32* __restrict__ alo,
    const u32* __restrict__ whi, const u32* __restrict__ wlo,
    int K, int N,
    float* __restrict__ Cf, u32* __restrict__ Chi, u32* __restrict__ Clo,
    const float* __restrict__ bias, const float* __restrict__ resid)
{
    constexpr int AR = 256 / (2 * NG);
    int khalf = K >> 1;
    int nchunks = K >> 4;
    __shared__ __align__(16) __nv_bfloat16 sAh[2][AR][24], sAl[2][AR][24],
                                           sWh[2][128][24], sWl[2][128][24];
    MMA_PROLOGUE(NG);
    int bm = blockIdx.y * AR, bn = blockIdx.x * 128;

    float acc[NF * 2][4];
#pragma unroll
    for (int j = 0; j < NF * 2; j++)
#pragma unroll
        for (int c = 0; c < 4; c++) acc[j][c] = 0.f;

    const uint4* gAh = (const uint4*)(ahi + (size_t)(bm + lrowA) * khalf) + lsegA;
    const uint4* gAl = (const uint4*)(alo + (size_t)(bm + lrowA) * khalf) + lsegA;
    const uint4* gWh = (const uint4*)(whi + (size_t)(bn + lrowW) * khalf) + lsegW;
    const uint4* gWl = (const uint4*)(wlo + (size_t)(bn + lrowW) * khalf) + lsegW;
    uint4 nah, nal;
    if (tid < MT2) { nah = gAh[0]; nal = gAl[0]; }
    uint4 nwh = gWh[0], nwl = gWl[0];
    MMA_CHUNK(acc, nchunks, NG);

    int q = lane & 3, r4 = lane >> 2;
#pragma unroll
    for (int p = 0; p < NF; p++)
#pragma unroll
        for (int s = 0; s < 2; s++) {
            int cb = bn + wn + p * 16 + s * 8 + 2 * q;
            float* A = acc[2 * p + s];
#pragma unroll
            for (int rh = 0; rh < 2; rh++) {
                size_t m = (size_t)(bm + wm + r4 + rh * 8);
                float v0 = A[rh * 2], v1 = A[rh * 2 + 1];
                if (MODE == 1) {
                    v0 = fmaxf(v0 + bias[cb], 0.f);
                    v1 = fmaxf(v1 + bias[cb + 1], 0.f);
                    u32 h, l;
                    splitpack(v0, v1, h, l);
                    Chi[m * (N >> 1) + (cb >> 1)] = h;
                    Clo[m * (N >> 1) + (cb >> 1)] = l;
                } else {
                    float2 r = *(const float2*)(resid + m * N + cb);
                    v0 += bias[cb] + r.x;
                    v1 += bias[cb + 1] + r.y;
                    *(float2*)(Cf + m * N + cb) = make_float2(v0, v1);
                }
            }
        }
}

// ================= LSTM step (NG=2, 64-row tiles; N=1024 live cols) =================
template<int FIRST, int LAST>
__global__ __launch_bounds__(256) void lstm_mma(
    const u32* __restrict__ ahi, const u32* __restrict__ alo,
    const u32* __restrict__ whi, const u32* __restrict__ wlo,
    float* __restrict__ qp, const float* __restrict__ pbias, const float* __restrict__ vr,
    float* __restrict__ cst, const float* __restrict__ qg,
    u32* __restrict__ ohi, u32* __restrict__ olo, float* __restrict__ of32)
{
    __shared__ __align__(16) __nv_bfloat16 sAh[2][64][24], sAl[2][64][24],
                                           sWh[2][128][24], sWl[2][128][24];
    MMA_PROLOGUE(2);
    int bm = blockIdx.y * 64, bn = blockIdx.x * 128;

    float acc[8][4];
#pragma unroll
    for (int j = 0; j < 8; j++)
#pragma unroll
        for (int c = 0; c < 4; c++) acc[j][c] = 0.f;

    const uint4* gAh = (const uint4*)(ahi + (size_t)(bm + lrowA) * 128) + lsegA;
    const uint4* gAl = (const uint4*)(alo + (size_t)(bm + lrowA) * 128) + lsegA;
    const uint4* gWh = (const uint4*)(whi + (size_t)(bn + lrowW) * 128) + lsegW;
    const uint4* gWl = (const uint4*)(wlo + (size_t)(bn + lrowW) * 128) + lsegW;
    uint4 nah, nal;
    if (tid < 128) { nah = gAh[0]; nal = gAl[0]; }
    uint4 nwh = gWh[0], nwl = gWl[0];
    MMA_CHUNK(acc, 16, 2);

    int q = lane & 3, r4 = lane >> 2;
#pragma unroll
    for (int p = 0; p < 4; p++) {
        int nblk = bn + wn + p * 16;
        int u = (nblk >> 4) * 4 + q;
        int n0 = nblk + 2 * q;
        float* A0 = acc[2 * p];
        float* A1 = acc[2 * p + 1];
#pragma unroll
        for (int rh = 0; rh < 2; rh++) {
            size_t m = (size_t)(bm + wm + r4 + rh * 8);
            float iv = A0[rh * 2], fv = A0[rh * 2 + 1];
            float gv = A1[rh * 2], ov = A1[rh * 2 + 1];
            if (FIRST) {
                iv += pbias[n0];     fv += pbias[n0 + 1];
                gv += pbias[n0 + 8]; ov += pbias[n0 + 9];
                *(float2*)(qp + m * NL + n0)     = make_float2(iv, fv);
                *(float2*)(qp + m * NL + n0 + 8) = make_float2(gv, ov);
            } else {
                float2 q1 = *(const float2*)(qp + m * NL + n0);
                float2 q2 = *(const float2*)(qp + m * NL + n0 + 8);
                iv += q1.x + vr[n0];     fv += q1.y + vr[n0 + 1];
                gv += q2.x + vr[n0 + 8]; ov += q2.y + vr[n0 + 9];
            }
            float cc;
            if (FIRST) cc = sigmf(iv) * tanhf(gv);
            else       cc = sigmf(fv) * cst[m * DM + u] + sigmf(iv) * tanhf(gv);
            cst[m * DM + u] = cc;
            float h = qg[m * DM + u] + sigmf(ov) * tanhf(cc);
            if (LAST) {
                of32[m * DM + u] = h;
            } else {
                __nv_bfloat16 hh = __float2bfloat16(h);
                __nv_bfloat16 hl = __float2bfloat16(h - __bfloat162float(hh));
                ((__nv_bfloat16*)ohi)[m * DM + u] = hh;
                ((__nv_bfloat16*)olo)[m * DM + u] = hl;
            }
        }
    }
}

// ================= fused LN (query rows) + support LN/mean/normalize =================
__global__ __launch_bounds__(256) void ln_kernel(const float* __restrict__ ln_g,
                                                 const float* __restrict__ ln_b) {
    __shared__ float red[8];
    __shared__ float srow[DM];
    int tid = threadIdx.x, lane = tid & 31, wid = tid >> 5;
    if (blockIdx.x == Bq) {
        float accg = 0.f;
        for (int r = 0; r < FEW; r++) {
            float z = g_qg[(size_t)(Bq + r) * DM + tid];
            float s1 = wred(z);
            if (lane == 0) red[wid] = s1;
            __syncthreads();
            float mu = (red[0] + red[1] + red[2] + red[3] + red[4] + red[5] + red[6] + red[7]) * (1.f / DM);
            __syncthreads();
            float dz = z - mu;
            float s2 = wred(dz * dz);
            if (lane == 0) red[wid] = s2;
            __syncthreads();
            float sig = sqrtf((red[0] + red[1] + red[2] + red[3] + red[4] + red[5] + red[6] + red[7]) * (1.f / (DM - 1)));
            accg += dz / (sig + 1e-3f) * ln_g[tid] + ln_b[tid];
            __syncthreads();
        }
        float sg = accg * (1.f / FEW);
        g_sg[tid] = sg;
        float s3 = wred(sg * sg);
        if (lane == 0) red[wid] = s3;
        __syncthreads();
        float nrm = sqrtf(red[0] + red[1] + red[2] + red[3] + red[4] + red[5] + red[6] + red[7]);
        g_sgn[tid] = sg / fmaxf(nrm, 1e-12f);
        return;
    }
    int row = blockIdx.x;
    float z = g_qg[(size_t)row * DM + tid];
    float s1 = wred(z);
    if (lane == 0) red[wid] = s1;
    __syncthreads();
    float mu = (red[0] + red[1] + red[2] + red[3] + red[4] + red[5] + red[6] + red[7]) * (1.f / DM);
    __syncthreads();
    float dz = z - mu;
    float s2 = wred(dz * dz);
    if (lane == 0) red[wid] = s2;
    __syncthreads();
    float sig = sqrtf((red[0] + red[1] + red[2] + red[3] + red[4] + red[5] + red[6] + red[7]) * (1.f / (DM - 1)));
    float o = dz / (sig + 1e-3f) * ln_g[tid] + ln_b[tid];
    g_qg[(size_t)row * DM + tid] = o;
    srow[tid] = o;
    __syncthreads();
    if (tid < 128) {
        u32 hi, lo;
        splitpack(srow[2 * tid], srow[2 * tid + 1], hi, lo);
        g_qghi[(size_t)row * 128 + tid] = hi;
        g_qglo[(size_t)row * 128 + tid] = lo;
    }
}

__global__ __launch_bounds__(256) void vr_kernel(
    const float* __restrict__ w_hh,
    const float* __restrict__ b_ih, const float* __restrict__ b_hh)
{
    int lane = threadIdx.x & 31, wid = threadIdx.x >> 5;
    int n = blockIdx.x * 8 + wid;
    int p = nperm_src(n);
    const float* w = w_hh + (size_t)p * HID + DM;
    float a = 0.f;
#pragma unroll
    for (int s = 0; s < 8; s++) a += w[lane + 32 * s] * g_sg[lane + 32 * s];
    a = wred(a);
    if (lane == 0) {
        g_vr[n] = a;
        g_pb[n] = b_ih[p] + b_hh[p];
    }
}

__global__ __launch_bounds__(256) void final_kernel(float* __restrict__ out) {
    int lane = threadIdx.x & 31, wid = threadIdx.x >> 5;
    int row = blockIdx.x * 8 + wid;
    const float* h = g_hb + (size_t)row * DM;
    float ss = 0.f, dt = 0.f;
#pragma unroll
    for (int s = 0; s < 8; s++) {
        float v = h[lane + 32 * s];
        ss += v * v;
        dt += v * g_sgn[lane + 32 * s];
    }
    ss = wred(ss); dt = wred(dt);
    if (lane == 0) out[row] = dt / fmaxf(sqrtf(ss), 1e-12f);
}

// ================= host =================
extern "C" void kernel_launch(void* const* d_in, const int* in_sizes, int n_in,
                              void* d_out, int out_size) {
    const int*   query   = (const int*)d_in[0];
    const int*   support = (const int*)d_in[1];
    const int*   qlc     = (const int*)d_in[2];
    const int*   qrc     = (const int*)d_in[4];
    const int*   slc     = (const int*)d_in[6];
    const int*   src_    = (const int*)d_in[8];
    const int*   knn     = (const int*)d_in[10];
    const float* emb     = (const float*)d_in[11];
    const float* gcn_w   = (const float*)d_in[12];
    const float* gcn_w_b = (const float*)d_in[13];
    const float* gcn_b   = (const float*)d_in[14];
    const float* gate_w  = (const float*)d_in[15];
    const float* gate_b  = (const float*)d_in[16];
    const float* p1_w    = (const float*)d_in[17];
    const float* p1_b    = (const float*)d_in[18];
    const float* p2_w    = (const float*)d_in[19];
    const float* p2_b    = (const float*)d_in[20];
    const float* ln_g    = (const float*)d_in[21];
    const float* ln_b    = (const float*)d_in[22];
    const float* w_ih    = (const float*)d_in[23];
    const float* w_hh    = (const float*)d_in[24];
    const float* b_ih    = (const float*)d_in[25];
    const float* b_hh    = (const float*)d_in[26];
    float* out = (float*)d_out;

    float *qg, *vr, *pb, *qp, *cst, *hb, *qn;
    u32 *wihh, *wihl, *whhh, *whhl, *qghi, *qglo, *hahi, *halo, *hbhi, *hblo;
    u32 *qnhi, *qnlo, *acthi, *actlo, *p1h, *p1l, *p2h, *p2l;
    cudaGetSymbolAddress((void**)&qn, g_qn);
    cudaGetSymbolAddress((void**)&qg, g_qg);
    cudaGetSymbolAddress((void**)&vr, g_vr);
    cudaGetSymbolAddress((void**)&pb, g_pb);
    cudaGetSymbolAddress((void**)&qp, g_qp);
    cudaGetSymbolAddress((void**)&cst, g_cst);
    cudaGetSymbolAddress((void**)&hb, g_hb);
    cudaGetSymbolAddress((void**)&wihh, g_wihh);
    cudaGetSymbolAddress((void**)&wihl, g_wihl);
    cudaGetSymbolAddress((void**)&whhh, g_whhh);
    cudaGetSymbolAddress((void**)&whhl, g_whhl);
    cudaGetSymbolAddress((void**)&qghi, g_qghi);
    cudaGetSymbolAddress((void**)&qglo, g_qglo);
    cudaGetSymbolAddress((void**)&hahi, g_hahi);
    cudaGetSymbolAddress((void**)&halo, g_halo);
    cudaGetSymbolAddress((void**)&hbhi, g_hbhi);
    cudaGetSymbolAddress((void**)&hblo, g_hblo);
    cudaGetSymbolAddress((void**)&qnhi, g_qnhi);
    cudaGetSymbolAddress((void**)&qnlo, g_qnlo);
    cudaGetSymbolAddress((void**)&acthi, g_acthi);
    cudaGetSymbolAddress((void**)&actlo, g_actlo);
    cudaGetSymbolAddress((void**)&p1h, g_p1h);
    cudaGetSymbolAddress((void**)&p1l, g_p1l);
    cudaGetSymbolAddress((void**)&p2h, g_p2h);
    cudaGetSymbolAddress((void**)&p2l, g_p2l);

    neigh_gather<<<NTASK + PREPB, 256>>>(query, support, qlc, qrc, slc, src_, knn, emb,
                                         w_ih, w_hh, gcn_w, p1_w, p2_w);
    gcn_fused<<<TPAD / 64, 256>>>(gcn_w_b, gcn_b, gate_w, gate_b);
    mma_gemm<1, 2><<<dim3(4, TQ / 64), 256>>>(
        qnhi, qnlo, p1h, p1l, 256, 512, nullptr, acthi, actlo, p1_b, nullptr);
    mma_gemm<2, 2><<<dim3(2, TQ / 64), 256>>>(
        acthi, actlo, p2h, p2l, 512, 256, qg, nullptr, nullptr, p2_b, qn);
    ln_kernel<<<Bq + 1, 256>>>(ln_g, ln_b);
    vr_kernel<<<NL / 8, 256>>>(w_hh, b_ih, b_hh);
    lstm_mma<1, 0><<<dim3(8, Bq / 64), 256>>>(qghi, qglo, wihh, wihl, qp, pb, vr, cst, qg,
                                              hahi, halo, nullptr);
    lstm_mma<0, 0><<<dim3(8, Bq / 64), 256>>>(hahi, halo, whhh, whhl, qp, pb, vr, cst, qg,
                                              hbhi, hblo, nullptr);
    lstm_mma<0, 0><<<dim3(8, Bq / 64), 256>>>(hbhi, hblo, whhh, whhl, qp, pb, vr, cst, qg,
                                              hahi, halo, nullptr);
    lstm_mma<0, 1><<<dim3(8, Bq / 64), 256>>>(hahi, halo, whhh, whhl, qp, pb, vr, cst, qg,
                                              nullptr, nullptr, hb);
    final_kernel<<<Bq / 8, 256>>>(out);
}

// round 16
// speedup vs baseline: 1.0412x; 1.0412x over previous
#include <cuda_runtime.h>
#include <cuda_bf16.h>
#include <math.h>
#include <cstdint>

#define D     128
#define Mn    128
#define KTAB  64
#define KSEL  32
#define Bq    2048
#define FEW   5
#define DM    256
#define HID   512
#define NL    1024
#define NTASK (2 * Bq + 2 * FEW)
#define TPAD  4224
#define TQ    2176
#define PREPB 1632

typedef unsigned long long ull;
typedef unsigned int u32;

// ================= scratch =================
__device__ __align__(128) float g_qn[TQ * DM];
__device__ __align__(128) float g_qg[TQ * DM];
__device__ __align__(128) float g_sg[DM];
__device__ __align__(128) float g_sgn[DM];
__device__ __align__(128) float g_vr[NL];
__device__ __align__(128) float g_pb[NL];
__device__ __align__(128) float g_qp[(size_t)Bq * NL];
__device__ __align__(128) float g_cst[Bq * DM];
__device__ __align__(128) float g_hb[Bq * DM];
__device__ __align__(128) u32 g_hshi[TPAD * 128];
__device__ __align__(128) u32 g_hslo[TPAD * 128];
__device__ __align__(128) u32 g_hkhi[TPAD * 64];
__device__ __align__(128) u32 g_hklo[TPAD * 64];
__device__ __align__(128) u32 g_qnhi[TQ * 128];
__device__ __align__(128) u32 g_qnlo[TQ * 128];
__device__ __align__(128) u32 g_acthi[TQ * 256];
__device__ __align__(128) u32 g_actlo[TQ * 256];
__device__ __align__(128) u32 g_qghi[Bq * 128];
__device__ __align__(128) u32 g_qglo[Bq * 128];
__device__ __align__(128) u32 g_hahi[Bq * 128];
__device__ __align__(128) u32 g_halo[Bq * 128];
__device__ __align__(128) u32 g_hbhi[Bq * 128];
__device__ __align__(128) u32 g_hblo[Bq * 128];
__device__ __align__(128) u32 g_wihh[NL * 128];
__device__ __align__(128) u32 g_wihl[NL * 128];
__device__ __align__(128) u32 g_whhh[NL * 128];
__device__ __align__(128) u32 g_whhl[NL * 128];
__device__ __align__(128) u32 g_gwh[128 * 128];
__device__ __align__(128) u32 g_gwl[128 * 128];
__device__ __align__(128) u32 g_gkh[128 * 64];
__device__ __align__(128) u32 g_gkl[128 * 64];
__device__ __align__(128) u32 g_p1h[512 * 128];
__device__ __align__(128) u32 g_p1l[512 * 128];
__device__ __align__(128) u32 g_p2h[256 * 256];
__device__ __align__(128) u32 g_p2l[256 * 256];

__device__ __forceinline__ float wred(float v) {
#pragma unroll
    for (int o = 16; o; o >>= 1) v += __shfl_xor_sync(0xffffffffu, v, o);
    return v;
}
__device__ __forceinline__ float sigmf(float x) { return 1.f / (1.f + expf(-x)); }
__device__ __forceinline__ void splitpack(float a, float b, u32& hi, u32& lo) {
    __nv_bfloat16 ha = __float2bfloat16(a), hb2 = __float2bfloat16(b);
    __nv_bfloat16 la = __float2bfloat16(a - __bfloat162float(ha));
    __nv_bfloat16 lb = __float2bfloat16(b - __bfloat162float(hb2));
    __nv_bfloat162 H; H.x = ha; H.y = hb2;
    __nv_bfloat162 L; L.x = la; L.y = lb;
    hi = *(u32*)&H; lo = *(u32*)&L;
}
__device__ __forceinline__ int nperm_src(int n) {
    int b = n >> 4, r = n & 15;
    int v = (r & 7) >> 1;
    int g = (r >> 3) * 2 + (r & 1);
    return g * 512 + b * 4 + v;
}
__device__ __forceinline__ u32 smem_u32(const void* p) {
    u32 a;
    asm("{ .reg .u64 t; cvta.to.shared.u64 t, %1; cvt.u32.u64 %0, t; }" : "=r"(a) : "l"(p));
    return a;
}
__device__ __forceinline__ void ldm4(u32* r, u32 addr) {
    asm volatile("ldmatrix.sync.aligned.m8n8.x4.shared.b16 {%0,%1,%2,%3}, [%4];"
                 : "=r"(r[0]), "=r"(r[1]), "=r"(r[2]), "=r"(r[3]) : "r"(addr));
}
__device__ __forceinline__ void mma16816(float* d, const u32* a, const u32* b) {
    asm volatile("mma.sync.aligned.m16n8k16.row.col.f32.bf16.bf16.f32 "
                 "{%0,%1,%2,%3},{%4,%5,%6,%7},{%8,%9},{%0,%1,%2,%3};"
                 : "+f"(d[0]), "+f"(d[1]), "+f"(d[2]), "+f"(d[3])
                 : "r"(a[0]), "r"(a[1]), "r"(a[2]), "r"(a[3]), "r"(b[0]), "r"(b[1]));
}

// ================= weight prep bodies =================
__device__ __forceinline__ void prep_perm_body(int idx, const float* w, int ldw,
                                               u32* hi, u32* lo) {
    int n = idx >> 7, kp = idx & 127;
    int srow = nperm_src(n);
    float v0 = w[(size_t)srow * ldw + 2 * kp];
    float v1 = w[(size_t)srow * ldw + 2 * kp + 1];
    u32 h, l;
    splitpack(v0, v1, h, l);
    hi[idx] = h; lo[idx] = l;
}
__device__ __forceinline__ void split_body(int idx, const float* w, int ldw, int off,
                                           int khalf, u32* hi, u32* lo) {
    int n = idx / khalf, kp = idx % khalf;
    float v0 = w[(size_t)n * ldw + off + 2 * kp];
    float v1 = w[(size_t)n * ldw + off + 2 * kp + 1];
    u32 h, l;
    splitpack(v0, v1, h, l);
    hi[idx] = h; lo[idx] = l;
}

// ================= neighbor gather + fused weight prep =================
__global__ __launch_bounds__(256) void neigh_gather(
    const int* __restrict__ query, const int* __restrict__ support,
    const int* __restrict__ qlc, const int* __restrict__ qrc,
    const int* __restrict__ slc, const int* __restrict__ src_,
    const int* __restrict__ knn, const float* __restrict__ emb,
    const float* __restrict__ w_ih, const float* __restrict__ w_hh,
    const float* __restrict__ gcn_w, const float* __restrict__ p1_w,
    const float* __restrict__ p2_w)
{
    __shared__ float s_center[D];
    __shared__ int   s_rid[Mn], s_eid[Mn];
    __shared__ float s_sim[Mn];
    __shared__ int   s_kid[KTAB];
    __shared__ float s_ksim[KTAB];
    __shared__ int   s_selr[KSEL], s_sele[KSEL], s_kselv[KSEL];
    __shared__ int   s_cnt, s_kcnt;
    __shared__ float s_cn;
    __shared__ float e_hs[DM];
    __shared__ float e_hk[D];

    if (blockIdx.x >= NTASK) {
        int b = blockIdx.x - NTASK, tid = threadIdx.x;
        if (b < 512)        prep_perm_body(b * 256 + tid, w_ih, DM, g_wihh, g_wihl);
        else if (b < 1024)  prep_perm_body((b - 512) * 256 + tid, w_hh, HID, g_whhh, g_whhl);
        else if (b < 1088)  split_body((b - 1024) * 256 + tid, gcn_w, 256, 0, 128, g_gwh, g_gwl);
        else if (b < 1120)  split_body((b - 1088) * 256 + tid, gcn_w, 256, 128, 64, g_gkh, g_gkl);
        else if (b < 1376)  split_body((b - 1120) * 256 + tid, p1_w, 256, 0, 128, g_p1h, g_p1l);
        else                split_body((b - 1376) * 256 + tid, p2_w, 512, 0, 256, g_p2h, g_p2l);
        return;
    }

    int task = blockIdx.x;
    const int* conn; int id;
    if (task < 2 * Bq) {
        int row = task & (Bq - 1);
        int br  = task >> 11;
        conn = (br ? qrc : qlc) + (size_t)row * Mn * 2;
        id   = query[row * 2 + br];
    } else {
        int t = task - 2 * Bq;
        int br = t / FEW, row = t % FEW;
        conn = (br ? src_ : slc) + (size_t)row * Mn * 2;
        id   = support[row * 2 + br];
    }
    int tid = threadIdx.x, lane = tid & 31, wid = tid >> 5;
    if (tid == 0) { s_cnt = 0; s_kcnt = 0; }
    if (tid < D)  s_center[tid] = emb[(size_t)id * D + tid];
    if (tid < Mn) { s_rid[tid] = conn[tid * 2]; s_eid[tid] = conn[tid * 2 + 1]; }
    if (tid >= 192) s_kid[tid - 192] = knn[(size_t)id * KTAB + (tid - 192)];
    __syncthreads();

    if (wid == 0) {
        float c0 = s_center[lane], c1 = s_center[lane + 32],
              c2 = s_center[lane + 64], c3 = s_center[lane + 96];
        float s = wred(c0 * c0 + c1 * c1 + c2 * c2 + c3 * c3);
        if (lane == 0) s_cn = sqrtf(s);
    }
    __syncthreads();
    float cn = s_cn;
    float4 cv = ((const float4*)s_center)[lane];

#pragma unroll
    for (int g = 0; g < 4; g++) {
        int m = wid * 16 + g * 4;
        float dt[4], nn[4];
#pragma unroll
        for (int t = 0; t < 4; t++) {
            float4 ev = ((const float4*)(emb + (size_t)s_eid[m + t] * D))[lane];
            dt[t] = ev.x * cv.x + ev.y * cv.y + ev.z * cv.z + ev.w * cv.w;
            nn[t] = ev.x * ev.x + ev.y * ev.y + ev.z * ev.z + ev.w * ev.w;
        }
#pragma unroll
        for (int o = 16; o; o >>= 1) {
#pragma unroll
            for (int t = 0; t < 4; t++) {
                dt[t] += __shfl_xor_sync(0xffffffffu, dt[t], o);
                nn[t] += __shfl_xor_sync(0xffffffffu, nn[t], o);
            }
        }
        if (lane == 0) {
#pragma unroll
            for (int t = 0; t < 4; t++)
                s_sim[m + t] = dt[t] / fmaxf(cn * sqrtf(nn[t]), 1e-8f);
        }
    }
#pragma unroll
    for (int g = 0; g < 2; g++) {
        int m = wid * 8 + g * 4;
        float dt[4], nn[4];
#pragma unroll
        for (int t = 0; t < 4; t++) {
            float4 ev = ((const float4*)(emb + (size_t)s_kid[m + t] * D))[lane];
            dt[t] = ev.x * cv.x + ev.y * cv.y + ev.z * cv.z + ev.w * cv.w;
            nn[t] = ev.x * ev.x + ev.y * ev.y + ev.z * ev.z + ev.w * ev.w;
        }
#pragma unroll
        for (int o = 16; o; o >>= 1) {
#pragma unroll
            for (int t = 0; t < 4; t++) {
                dt[t] += __shfl_xor_sync(0xffffffffu, dt[t], o);
                nn[t] += __shfl_xor_sync(0xffffffffu, nn[t], o);
            }
        }
        if (lane == 0) {
#pragma unroll
            for (int t = 0; t < 4; t++)
                s_ksim[m + t] = dt[t] / fmaxf(cn * sqrtf(nn[t]), 1e-8f);
        }
    }
    __syncthreads();

    if (tid < Mn) {
        float v = s_sim[tid]; int r = 0;
        for (int j = 0; j < Mn; j++) {
            float u = s_sim[j];
            r += (u > v) || (u == v && j < tid);
        }
        if (r < KSEL) {
            int p = atomicAdd(&s_cnt, 1);
            s_selr[p] = s_rid[tid];
            s_sele[p] = s_eid[tid];
        }
    } else if (tid < Mn + KTAB) {
        int m = tid - Mn;
        float v = s_ksim[m]; int r = 0;
        for (int j = 0; j < KTAB; j++) {
            float u = s_ksim[j];
            r += (u > v) || (u == v && j < m);
        }
        if (r < KSEL) {
            int p = atomicAdd(&s_kcnt, 1);
            s_kselv[p] = s_kid[m];
        }
    }
    __syncthreads();

    int d = tid & (D - 1);
    if (tid < D) {
        float acc = 0.f;
#pragma unroll 8
        for (int i = 0; i < KSEL; i++) acc += emb[(size_t)s_selr[i] * D + d];
        e_hs[d] = acc * (1.f / KSEL);
        float ak = 0.f;
#pragma unroll 8
        for (int i = 0; i < KSEL; i++) ak += emb[(size_t)s_kselv[i] * D + d];
        e_hk[d] = ak * (1.f / KSEL);
    } else {
        float acc = 0.f;
#pragma unroll 8
        for (int i = 0; i < KSEL; i++) acc += emb[(size_t)s_sele[i] * D + d];
        e_hs[D + d] = acc * (1.f / KSEL);
    }
    __syncthreads();
    if (tid < 128) {
        u32 hi, lo;
        splitpack(e_hs[2 * tid], e_hs[2 * tid + 1], hi, lo);
        g_hshi[(size_t)task * 128 + tid] = hi;
        g_hslo[(size_t)task * 128 + tid] = lo;
    } else if (tid < 192) {
        int t2 = tid - 128;
        u32 hi, lo;
        splitpack(e_hk[2 * t2], e_hk[2 * t2 + 1], hi, lo);
        g_hkhi[(size_t)task * 64 + t2] = hi;
        g_hklo[(size_t)task * 64 + t2] = lo;
    }
}

// ================= double-buffered pipelined mma mainloop =================
#define MMA_PROLOGUE(NG) \
    int tid = threadIdx.x, lane = tid & 31, w = tid >> 5; \
    int wm = (w / (NG)) * 16, wn = (w % (NG)) * (128 / (NG)); \
    constexpr int NF = 128 / (NG) / 16; \
    constexpr int MT2 = (8 / (NG)) * 32; \
    int lrowW = tid >> 1, lsegW = tid & 1; \
    int lrowA = (tid & (MT2 - 1)) >> 1, lsegA = tid & 1; \
    u32 soffW = (u32)(lrowW * 24 + lsegW * 8) * 2; \
    u32 soffA = (u32)(lrowA * 24 + lsegA * 8) * 2; \
    u32 bAh = smem_u32(sAh), bAl = smem_u32(sAl), bWh = smem_u32(sWh), bWl = smem_u32(sWl); \
    u32 abufB = (u32)(MT2 / 2) * 24u * 2u; \
    u32 wbufB = 128u * 24u * 2u; \
    u32 aoff = (u32)((wm + (lane & 15)) * 24 + (lane >> 4) * 8) * 2; \
    u32 boff[NF]; \
    _Pragma("unroll") \
    for (int nf = 0; nf < NF; nf++) { \
        int g = lane >> 3; \
        int row = wn + nf * 16 + (lane & 7) + (g >> 1) * 8; \
        int col = (g & 1) * 8; \
        boff[nf] = (u32)(row * 24 + col) * 2; \
    }

#define MMA_CHUNK(ACC, NCH, NG) \
    { \
        constexpr int NFc = 128 / (NG) / 16; \
        constexpr int MT2c = (8 / (NG)) * 32; \
        if (tid < MT2c) { \
            *(uint4*)((char*)sAh + soffA) = nah; \
            *(uint4*)((char*)sAl + soffA) = nal; \
        } \
        *(uint4*)((char*)sWh + soffW) = nwh; \
        *(uint4*)((char*)sWl + soffW) = nwl; \
        if (1 < (NCH)) { \
            if (tid < MT2c) { nah = gAh[2]; nal = gAl[2]; } \
            nwh = gWh[2]; nwl = gWl[2]; \
        } \
        __syncthreads(); \
        for (int kc = 0; kc < (NCH); kc++) { \
            u32 cb_ = (u32)(kc & 1), nb_ = cb_ ^ 1u; \
            if (kc + 1 < (NCH)) { \
                if (tid < MT2c) { \
                    *(uint4*)((char*)sAh + nb_ * abufB + soffA) = nah; \
                    *(uint4*)((char*)sAl + nb_ * abufB + soffA) = nal; \
                } \
                *(uint4*)((char*)sWh + nb_ * wbufB + soffW) = nwh; \
                *(uint4*)((char*)sWl + nb_ * wbufB + soffW) = nwl; \
            } \
            if (kc + 2 < (NCH)) { \
                if (tid < MT2c) { nah = gAh[(kc + 2) * 2]; nal = gAl[(kc + 2) * 2]; } \
                nwh = gWh[(kc + 2) * 2]; nwl = gWl[(kc + 2) * 2]; \
            } \
            u32 ah[4], al[4], wf[NFc][4]; \
            ldm4(ah, bAh + cb_ * abufB + aoff); \
            ldm4(al, bAl + cb_ * abufB + aoff); \
            _Pragma("unroll") \
            for (int nf = 0; nf < NFc; nf++) ldm4(wf[nf], bWh + cb_ * wbufB + boff[nf]); \
            _Pragma("unroll") \
            for (int nf = 0; nf < NFc; nf++) { \
                mma16816(ACC[nf * 2],     ah, wf[nf]); \
                mma16816(ACC[nf * 2 + 1], ah, wf[nf] + 2); \
                mma16816(ACC[nf * 2],     al, wf[nf]); \
                mma16816(ACC[nf * 2 + 1], al, wf[nf] + 2); \
            } \
            _Pragma("unroll") \
            for (int nf = 0; nf < NFc; nf++) ldm4(wf[nf], bWl + cb_ * wbufB + boff[nf]); \
            _Pragma("unroll") \
            for (int nf = 0; nf < NFc; nf++) { \
                mma16816(ACC[nf * 2],     ah, wf[nf]); \
                mma16816(ACC[nf * 2 + 1], ah, wf[nf] + 2); \
            } \
            __syncthreads(); \
        } \
    }

// ================= fused GCN dual GEMM + combine (NG=4, 32-row tiles; R14 config) =================
__global__ __launch_bounds__(256) void gcn_fused(
    const float* __restrict__ gcn_w_b, const float* __restrict__ gcn_b,
    const float* __restrict__ gate_w, const float* __restrict__ gate_b)
{
    __shared__ __align__(16) __nv_bfloat16 sAh[2][32][24], sAl[2][32][24],
                                           sWh[2][128][24], sWl[2][128][24];
    __shared__ float s_part[8][16];
    MMA_PROLOGUE(4);
    int bm = blockIdx.x * 32;

    float acc1[4][4], acc2[4][4];
#pragma unroll
    for (int j = 0; j < 4; j++)
#pragma unroll
        for (int c = 0; c < 4; c++) { acc1[j][c] = 0.f; acc2[j][c] = 0.f; }

    {
        const uint4* gAh = (const uint4*)(g_hshi + (size_t)(bm + lrowA) * 128) + lsegA;
        const uint4* gAl = (const uint4*)(g_hslo + (size_t)(bm + lrowA) * 128) + lsegA;
        const uint4* gWh = (const uint4*)(g_gwh + (size_t)lrowW * 128) + lsegW;
        const uint4* gWl = (const uint4*)(g_gwl + (size_t)lrowW * 128) + lsegW;
        uint4 nah, nal;
        if (tid < 64) { nah = gAh[0]; nal = gAl[0]; }
        uint4 nwh = gWh[0], nwl = gWl[0];
        MMA_CHUNK(acc1, 16, 4);
    }
    {
        const uint4* gAh = (const uint4*)(g_hkhi + (size_t)(bm + lrowA) * 64) + lsegA;
        const uint4* gAl = (const uint4*)(g_hklo + (size_t)(bm + lrowA) * 64) + lsegA;
        const uint4* gWh = (const uint4*)(g_gkh + (size_t)lrowW * 64) + lsegW;
        const uint4* gWl = (const uint4*)(g_gkl + (size_t)lrowW * 64) + lsegW;
        uint4 nah, nal;
        if (tid < 64) { nah = gAh[0]; nal = gAl[0]; }
        uint4 nwh = gWh[0], nwl = gWl[0];
        MMA_CHUNK(acc2, 8, 4);
    }

    int q = lane & 3, r4 = lane >> 2;
    float part[2] = {0.f, 0.f};
#pragma unroll
    for (int p = 0; p < 2; p++)
#pragma unroll
        for (int s = 0; s < 2; s++)
#pragma unroll
            for (int c = 0; c < 2; c++) {
                int col = wn + p * 16 + s * 8 + 2 * q + c;
                float wbgb = gcn_w_b[col] + gcn_b[col];
                float gws = gate_w[col], gwk = gate_w[D + col];
#pragma unroll
                for (int rh = 0; rh < 2; rh++) {
                    float sv = tanhf(acc1[2 * p + s][rh * 2 + c] + wbgb);
                    float kv = tanhf(acc2[2 * p + s][rh * 2 + c] + wbgb);
                    acc1[2 * p + s][rh * 2 + c] = sv;
                    acc2[2 * p + s][rh * 2 + c] = kv;
                    part[rh] += gws * sv + gwk * kv;
                }
            }
#pragma unroll
    for (int rh = 0; rh < 2; rh++) {
        float v = part[rh];
        v += __shfl_xor_sync(0xffffffffu, v, 1);
        v += __shfl_xor_sync(0xffffffffu, v, 2);
        part[rh] = v;
    }
    if (q == 0) {
#pragma unroll
        for (int rh = 0; rh < 2; rh++)
            s_part[w][rh * 8 + r4] = part[rh];
    }
    __syncthreads();
    float gb0 = gate_b[0];
    int mg = w >> 2;
#pragma unroll
    for (int rh = 0; rh < 2; rh++) {
        int rl = rh * 8 + r4;
        float tot = s_part[mg * 4 + 0][rl] + s_part[mg * 4 + 1][rl]
                  + s_part[mg * 4 + 2][rl] + s_part[mg * 4 + 3][rl];
        float al = sigmf(tot + gb0);
        int t = bm + wm + r4 + rh * 8;
        int rowq, half;
        if (t < 2 * Bq) { rowq = t & (Bq - 1); half = t >> 11; }
        else if (t < NTASK) { int t2 = t - 2 * Bq; rowq = Bq + t2 % FEW; half = t2 / FEW; }
        else continue;
#pragma unroll
        for (int p = 0; p < 2; p++)
#pragma unroll
            for (int s = 0; s < 2; s++) {
                int col = wn + p * 16 + s * 8 + 2 * q;
                float o0 = (1.f - al) * acc1[2 * p + s][rh * 2]
                         + al * acc2[2 * p + s][rh * 2];
                float o1 = (1.f - al) * acc1[2 * p + s][rh * 2 + 1]
                         + al * acc2[2 * p + s][rh * 2 + 1];
                int colq = half * 128 + col;
                *(float2*)(g_qn + (size_t)rowq * DM + colq) = make_float2(o0, o1);
                u32 h, l;
                splitpack(o0, o1, h, l);
                g_qnhi[(size_t)rowq * 128 + (colq >> 1)] = h;
                g_qnlo[(size_t)rowq * 128 + (colq >> 1)] = l;
            }
    }
}

// ================= generic bf16-split mma GEMM (templated NG) =================
template<int MODE, int NG>
__global__ __launch_bounds__(256) void mma_gemm(
    const u32* __restrict__ ahi, const u32* __restrict__ alo,
    const u32* __restrict__ whi, const u32* __restrict__ wlo,
    int K, int N,
    float* __restrict__ Cf, u32* __restrict__ Chi, u32* __restrict__ Clo,
    const float* __restrict__ bias, const float* __restrict__ resid)
{
    constexpr int AR = 256 / (2 * NG);
    int khalf = K >> 1;
    int nchunks = K >> 4;
    __shared__ __align__(16) __nv_bfloat16 sAh[2][AR][24], sAl[2][AR][24],
                                           sWh[2][128][24], sWl[2][128][24];
    MMA_PROLOGUE(NG);
    int bm = blockIdx.y * AR, bn = blockIdx.x * 128;

    float acc[NF * 2][4];
#pragma unroll
    for (int j = 0; j < NF * 2; j++)
#pragma unroll
        for (int c = 0; c < 4; c++) acc[j][c] = 0.f;

    const uint4* gAh = (const uint4*)(ahi + (size_t)(bm + lrowA) * khalf) + lsegA;
    const uint4* gAl = (const uint4*)(alo + (size_t)(bm + lrowA) * khalf) + lsegA;
    const uint4* gWh = (const uint4*)(whi + (size_t)(bn + lrowW) * khalf) + lsegW;
    const uint4* gWl = (const uint4*)(wlo + (size_t)(bn + lrowW) * khalf) + lsegW;
    uint4 nah, nal;
    if (tid < MT2) { nah = gAh[0]; nal = gAl[0]; }
    uint4 nwh = gWh[0], nwl = gWl[0];
    MMA_CHUNK(acc, nchunks, NG);

    int q = lane & 3, r4 = lane >> 2;
#pragma unroll
    for (int p = 0; p < NF; p++)
#pragma unroll
        for (int s = 0; s < 2; s++) {
            int cb = bn + wn + p * 16 + s * 8 + 2 * q;
            float* A = acc[2 * p + s];
#pragma unroll
            for (int rh = 0; rh < 2; rh++) {
                size_t m = (size_t)(bm + wm + r4 + rh * 8);
                float v0 = A[rh * 2], v1 = A[rh * 2 + 1];
                if (MODE == 1) {
                    v0 = fmaxf(v0 + bias[cb], 0.f);
                    v1 = fmaxf(v1 + bias[cb + 1], 0.f);
                    u32 h, l;
                    splitpack(v0, v1, h, l);
                    Chi[m * (N >> 1) + (cb >> 1)] = h;
                    Clo[m * (N >> 1) + (cb >> 1)] = l;
                } else {
                    float2 r = *(const float2*)(resid + m * N + cb);
                    v0 += bias[cb] + r.x;
                    v1 += bias[cb + 1] + r.y;
                    *(float2*)(Cf + m * N + cb) = make_float2(v0, v1);
                }
            }
        }
}

// ================= LSTM step (NG=2, 64-row tiles; N=1024 live cols) =================
template<int FIRST, int LAST>
__global__ __launch_bounds__(256) void lstm_mma(
    const u32* __restrict__ ahi, const u32* __restrict__ alo,
    const u32* __restrict__ whi, const u32* __restrict__ wlo,
    float* __restrict__ qp, const float* __restrict__ pbias, const float* __restrict__ vr,
    float* __restrict__ cst, const float* __restrict__ qg,
    u32* __restrict__ ohi, u32* __restrict__ olo, float* __restrict__ of32)
{
    __shared__ __align__(16) __nv_bfloat16 sAh[2][64][24], sAl[2][64][24],
                                           sWh[2][128][24], sWl[2][128][24];
    MMA_PROLOGUE(2);
    int bm = blockIdx.y * 64, bn = blockIdx.x * 128;

    float acc[8][4];
#pragma unroll
    for (int j = 0; j < 8; j++)
#pragma unroll
        for (int c = 0; c < 4; c++) acc[j][c] = 0.f;

    const uint4* gAh = (const uint4*)(ahi + (size_t)(bm + lrowA) * 128) + lsegA;
    const uint4* gAl = (const uint4*)(alo + (size_t)(bm + lrowA) * 128) + lsegA;
    const uint4* gWh = (const uint4*)(whi + (size_t)(bn + lrowW) * 128) + lsegW;
    const uint4* gWl = (const uint4*)(wlo + (size_t)(bn + lrowW) * 128) + lsegW;
    uint4 nah, nal;
    if (tid < 128) { nah = gAh[0]; nal = gAl[0]; }
    uint4 nwh = gWh[0], nwl = gWl[0];
    MMA_CHUNK(acc, 16, 2);

    int q = lane & 3, r4 = lane >> 2;
#pragma unroll
    for (int p = 0; p < 4; p++) {
        int nblk = bn + wn + p * 16;
        int u = (nblk >> 4) * 4 + q;
        int n0 = nblk + 2 * q;
        float* A0 = acc[2 * p];
        float* A1 = acc[2 * p + 1];
#pragma unroll
        for (int rh = 0; rh < 2; rh++) {
            size_t m = (size_t)(bm + wm + r4 + rh * 8);
            float iv = A0[rh * 2], fv = A0[rh * 2 + 1];
            float gv = A1[rh * 2], ov = A1[rh * 2 + 1];
            if (FIRST) {
                iv += pbias[n0];     fv += pbias[n0 + 1];
                gv += pbias[n0 + 8]; ov += pbias[n0 + 9];
                *(float2*)(qp + m * NL + n0)     = make_float2(iv, fv);
                *(float2*)(qp + m * NL + n0 + 8) = make_float2(gv, ov);
            } else {
                float2 q1 = *(const float2*)(qp + m * NL + n0);
                float2 q2 = *(const float2*)(qp + m * NL + n0 + 8);
                iv += q1.x + vr[n0];     fv += q1.y + vr[n0 + 1];
                gv += q2.x + vr[n0 + 8]; ov += q2.y + vr[n0 + 9];
            }
            float cc;
            if (FIRST) cc = sigmf(iv) * tanhf(gv);
            else       cc = sigmf(fv) * cst[m * DM + u] + sigmf(iv) * tanhf(gv);
            cst[m * DM + u] = cc;
            float h = qg[m * DM + u] + sigmf(ov) * tanhf(cc);
            if (LAST) {
                of32[m * DM + u] = h;
            } else {
                __nv_bfloat16 hh = __float2bfloat16(h);
                __nv_bfloat16 hl = __float2bfloat16(h - __bfloat162float(hh));
                ((__nv_bfloat16*)ohi)[m * DM + u] = hh;
                ((__nv_bfloat16*)olo)[m * DM + u] = hl;
            }
        }
    }
}

// ================= LN: warp-per-row (8 rows/block) + support block =================
__global__ __launch_bounds__(256) void ln_kernel(const float* __restrict__ ln_g,
                                                 const float* __restrict__ ln_b) {
    int tid = threadIdx.x, lane = tid & 31, wid = tid >> 5;
    if (blockIdx.x == Bq / 8) {
        __shared__ float red[8];
        float accg = 0.f;
        for (int r = 0; r < FEW; r++) {
            float z = g_qg[(size_t)(Bq + r) * DM + tid];
            float s1 = wred(z);
            if (lane == 0) red[wid] = s1;
            __syncthreads();
            float mu = (red[0] + red[1] + red[2] + red[3] + red[4] + red[5] + red[6] + red[7]) * (1.f / DM);
            __syncthreads();
            float dz = z - mu;
            float s2 = wred(dz * dz);
            if (lane == 0) red[wid] = s2;
            __syncthreads();
            float sig = sqrtf((red[0] + red[1] + red[2] + red[3] + red[4] + red[5] + red[6] + red[7]) * (1.f / (DM - 1)));
            accg += dz / (sig + 1e-3f) * ln_g[tid] + ln_b[tid];
            __syncthreads();
        }
        float sg = accg * (1.f / FEW);
        g_sg[tid] = sg;
        float s3 = wred(sg * sg);
        if (lane == 0) red[wid] = s3;
        __syncthreads();
        float nrm = sqrtf(red[0] + red[1] + red[2] + red[3] + red[4] + red[5] + red[6] + red[7]);
        g_sgn[tid] = sg / fmaxf(nrm, 1e-12f);
        return;
    }
    // warp-per-row LN (no block syncs)
    int row = blockIdx.x * 8 + wid;
    const float2* zp = (const float2*)(g_qg + (size_t)row * DM);
    float2 z[4];
    float s1 = 0.f;
#pragma unroll
    for (int s = 0; s < 4; s++) {
        z[s] = zp[lane + 32 * s];
        s1 += z[s].x + z[s].y;
    }
    s1 = wred(s1);
    float mu = s1 * (1.f / DM);
    float s2 = 0.f;
#pragma unroll
    for (int s = 0; s < 4; s++) {
        z[s].x -= mu; z[s].y -= mu;
        s2 += z[s].x * z[s].x + z[s].y * z[s].y;
    }
    s2 = wred(s2);
    float inv = 1.f / (sqrtf(s2 * (1.f / (DM - 1))) + 1e-3f);
#pragma unroll
    for (int s = 0; s < 4; s++) {
        int cu = lane + 32 * s;
        int c = cu * 2;
        float o0 = z[s].x * inv * ln_g[c] + ln_b[c];
        float o1 = z[s].y * inv * ln_g[c + 1] + ln_b[c + 1];
        *(float2*)(g_qg + (size_t)row * DM + c) = make_float2(o0, o1);
        u32 hi, lo;
        splitpack(o0, o1, hi, lo);
        g_qghi[(size_t)row * 128 + cu] = hi;
        g_qglo[(size_t)row * 128 + cu] = lo;
    }
}

__global__ __launch_bounds__(256) void vr_kernel(
    const float* __restrict__ w_hh,
    const float* __restrict__ b_ih, const float* __restrict__ b_hh)
{
    int lane = threadIdx.x & 31, wid = threadIdx.x >> 5;
    int n = blockIdx.x * 8 + wid;
    int p = nperm_src(n);
    const float* w = w_hh + (size_t)p * HID + DM;
    float a = 0.f;
#pragma unroll
    for (int s = 0; s < 8; s++) a += w[lane + 32 * s] * g_sg[lane + 32 * s];
    a = wred(a);
    if (lane == 0) {
        g_vr[n] = a;
        g_pb[n] = b_ih[p] + b_hh[p];
    }
}

__global__ __launch_bounds__(256) void final_kernel(float* __restrict__ out) {
    int lane = threadIdx.x & 31, wid = threadIdx.x >> 5;
    int row = blockIdx.x * 8 + wid;
    const float* h = g_hb + (size_t)row * DM;
    float ss = 0.f, dt = 0.f;
#pragma unroll
    for (int s = 0; s < 8; s++) {
        float v = h[lane + 32 * s];
        ss += v * v;
        dt += v * g_sgn[lane + 32 * s];
    }
    ss = wred(ss); dt = wred(dt);
    if (lane == 0) out[row] = dt / fmaxf(sqrtf(ss), 1e-12f);
}

// ================= host =================
extern "C" void kernel_launch(void* const* d_in, const int* in_sizes, int n_in,
                              void* d_out, int out_size) {
    const int*   query   = (const int*)d_in[0];
    const int*   support = (const int*)d_in[1];
    const int*   qlc     = (const int*)d_in[2];
    const int*   qrc     = (const int*)d_in[4];
    const int*   slc     = (const int*)d_in[6];
    const int*   src_    = (const int*)d_in[8];
    const int*   knn     = (const int*)d_in[10];
    const float* emb     = (const float*)d_in[11];
    const float* gcn_w   = (const float*)d_in[12];
    const float* gcn_w_b = (const float*)d_in[13];
    const float* gcn_b   = (const float*)d_in[14];
    const float* gate_w  = (const float*)d_in[15];
    const float* gate_b  = (const float*)d_in[16];
    const float* p1_w    = (const float*)d_in[17];
    const float* p1_b    = (const float*)d_in[18];
    const float* p2_w    = (const float*)d_in[19];
    const float* p2_b    = (const float*)d_in[20];
    const float* ln_g    = (const float*)d_in[21];
    const float* ln_b    = (const float*)d_in[22];
    const float* w_ih    = (const float*)d_in[23];
    const float* w_hh    = (const float*)d_in[24];
    const float* b_ih    = (const float*)d_in[25];
    const float* b_hh    = (const float*)d_in[26];
    float* out = (float*)d_out;

    float *qg, *vr, *pb, *qp, *cst, *hb, *qn;
    u32 *wihh, *wihl, *whhh, *whhl, *qghi, *qglo, *hahi, *halo, *hbhi, *hblo;
    u32 *qnhi, *qnlo, *acthi, *actlo, *p1h, *p1l, *p2h, *p2l;
    cudaGetSymbolAddress((void**)&qn, g_qn);
    cudaGetSymbolAddress((void**)&qg, g_qg);
    cudaGetSymbolAddress((void**)&vr, g_vr);
    cudaGetSymbolAddress((void**)&pb, g_pb);
    cudaGetSymbolAddress((void**)&qp, g_qp);
    cudaGetSymbolAddress((void**)&cst, g_cst);
    cudaGetSymbolAddress((void**)&hb, g_hb);
    cudaGetSymbolAddress((void**)&wihh, g_wihh);
    cudaGetSymbolAddress((void**)&wihl, g_wihl);
    cudaGetSymbolAddress((void**)&whhh, g_whhh);
    cudaGetSymbolAddress((void**)&whhl, g_whhl);
    cudaGetSymbolAddress((void**)&qghi, g_qghi);
    cudaGetSymbolAddress((void**)&qglo, g_qglo);
    cudaGetSymbolAddress((void**)&hahi, g_hahi);
    cudaGetSymbolAddress((void**)&halo, g_halo);
    cudaGetSymbolAddress((void**)&hbhi, g_hbhi);
    cudaGetSymbolAddress((void**)&hblo, g_hblo);
    cudaGetSymbolAddress((void**)&qnhi, g_qnhi);
    cudaGetSymbolAddress((void**)&qnlo, g_qnlo);
    cudaGetSymbolAddress((void**)&acthi, g_acthi);
    cudaGetSymbolAddress((void**)&actlo, g_actlo);
    cudaGetSymbolAddress((void**)&p1h, g_p1h);
    cudaGetSymbolAddress((void**)&p1l, g_p1l);
    cudaGetSymbolAddress((void**)&p2h, g_p2h);
    cudaGetSymbolAddress((void**)&p2l, g_p2l);

    neigh_gather<<<NTASK + PREPB, 256>>>(query, support, qlc, qrc, slc, src_, knn, emb,
                                         w_ih, w_hh, gcn_w, p1_w, p2_w);
    gcn_fused<<<TPAD / 32, 256>>>(gcn_w_b, gcn_b, gate_w, gate_b);
    mma_gemm<1, 2><<<dim3(4, TQ / 64), 256>>>(
        qnhi, qnlo, p1h, p1l, 256, 512, nullptr, acthi, actlo, p1_b, nullptr);
    mma_gemm<2, 4><<<dim3(2, TQ / 32), 256>>>(
        acthi, actlo, p2h, p2l, 512, 256, qg, nullptr, nullptr, p2_b, qn);
    ln_kernel<<<Bq / 8 + 1, 256>>>(ln_g, ln_b);
    vr_kernel<<<NL / 8, 256>>>(w_hh, b_ih, b_hh);
    lstm_mma<1, 0><<<dim3(8, Bq / 64), 256>>>(qghi, qglo, wihh, wihl, qp, pb, vr, cst, qg,
                                              hahi, halo, nullptr);
    lstm_mma<0, 0><<<dim3(8, Bq / 64), 256>>>(hahi, halo, whhh, whhl, qp, pb, vr, cst, qg,
                                              hbhi, hblo, nullptr);
    lstm_mma<0, 0><<<dim3(8, Bq / 64), 256>>>(hbhi, hblo, whhh, whhl, qp, pb, vr, cst, qg,
                                              hahi, halo, nullptr);
    lstm_mma<0, 1><<<dim3(8, Bq / 64), 256>>>(hahi, halo, whhh, whhl, qp, pb, vr, cst, qg,
                                              nullptr, nullptr, hb);
    final_kernel<<<Bq / 8, 256>>>(out);
}